// round 2
// baseline (speedup 1.0000x reference)
#include <cuda_runtime.h>
#include <math.h>

#define NNODES 50000
#define RREL 3
#define EEDGE 50000

// ---------------- scratch (device globals; no allocation allowed) ----------
__device__ float g_hA[(size_t)NNODES * 512];
__device__ float g_hB[(size_t)NNODES * 512];
__device__ float g_hr[(size_t)NNODES * 512];
__device__ float g_sn[RREL * NNODES];
__device__ float g_dn[RREL * NNODES];
__device__ float g_coef[RREL * EEDGE];

// ---------------- small utility kernels ------------------------------------
__global__ void zero_kernel(float* __restrict__ p, int n) {
    int i = blockIdx.x * blockDim.x + threadIdx.x;
    if (i < n) p[i] = 0.0f;
}

__global__ void deg_kernel(const int* __restrict__ src, const int* __restrict__ dst,
                           float* __restrict__ outdeg, float* __restrict__ indeg,
                           int E, int N) {
    int i = blockIdx.x * blockDim.x + threadIdx.x;
    if (i < RREL * E) {
        int r = i / E;
        atomicAdd(&outdeg[r * N + src[i]], 1.0f);
        atomicAdd(&indeg[r * N + dst[i]], 1.0f);
    }
}

__global__ void norm_kernel(float* __restrict__ p, int n) {
    int i = blockIdx.x * blockDim.x + threadIdx.x;
    if (i < n) p[i] = rsqrtf(fmaxf(p[i], 1.0f));
}

// coef[r*E + e] = sn_r[src] * dn_r[dst]
__global__ void coef_kernel(const int* __restrict__ src, const int* __restrict__ dst,
                            const float* __restrict__ sn, const float* __restrict__ dn,
                            float* __restrict__ coef, int E, int N) {
    int i = blockIdx.x * blockDim.x + threadIdx.x;
    if (i < RREL * E) {
        int r = i / E;
        coef[i] = sn[r * N + src[i]] * dn[r * N + dst[i]];
    }
}

// ---------------- tiled fp32 SGEMM: C[M,Nc] = A[M,K] @ B[K,Nc] --------------
// BM=128, BN=64, BK=16, 256 threads, each thread computes 8x4.
#define BM 128
#define BN 64
#define BK 16
#define TM 8
#define TN 4

__global__ __launch_bounds__(256) void sgemm_kernel(
    const float* __restrict__ A, const float* __restrict__ B,
    float* __restrict__ C, int M, int K, int Nc) {
    __shared__ float As[BK][BM];
    __shared__ float Bs[BK][BN];

    const int tid  = threadIdx.x;
    const int trow = tid >> 4;          // 0..15
    const int tcol = tid & 15;          // 0..15
    const int rowBase = blockIdx.y * BM;
    const int colBase = blockIdx.x * BN;

    float acc[TM][TN];
#pragma unroll
    for (int i = 0; i < TM; i++)
#pragma unroll
        for (int j = 0; j < TN; j++) acc[i][j] = 0.0f;

    const int bRow = tid >> 4;          // 0..15
    const int bCol = (tid & 15) * 4;    // 0..60

    for (int k0 = 0; k0 < K; k0 += BK) {
        // Load A tile: 128 rows x 16 cols, via 512 float4 chunks (2 per thread)
#pragma unroll
        for (int t = 0; t < 2; t++) {
            int c  = tid + t * 256;
            int r  = c >> 2;            // 0..127
            int kk = (c & 3) * 4;       // 0,4,8,12
            int gr = rowBase + r;
            float4 v = make_float4(0.f, 0.f, 0.f, 0.f);
            if (gr < M) v = *(const float4*)(A + (size_t)gr * K + k0 + kk);
            As[kk + 0][r] = v.x;
            As[kk + 1][r] = v.y;
            As[kk + 2][r] = v.z;
            As[kk + 3][r] = v.w;
        }
        // Load B tile: 16 rows x 64 cols, one float4 per thread
        {
            float4 v = *(const float4*)(B + (size_t)(k0 + bRow) * Nc + colBase + bCol);
            *(float4*)&Bs[bRow][bCol] = v;
        }
        __syncthreads();

#pragma unroll
        for (int k = 0; k < BK; k++) {
            float a[TM], b[TN];
            float4 a0 = *(const float4*)&As[k][trow * TM + 0];
            float4 a1 = *(const float4*)&As[k][trow * TM + 4];
            a[0]=a0.x; a[1]=a0.y; a[2]=a0.z; a[3]=a0.w;
            a[4]=a1.x; a[5]=a1.y; a[6]=a1.z; a[7]=a1.w;
            float4 b0 = *(const float4*)&Bs[k][tcol * TN];
            b[0]=b0.x; b[1]=b0.y; b[2]=b0.z; b[3]=b0.w;
#pragma unroll
            for (int i = 0; i < TM; i++)
#pragma unroll
                for (int j = 0; j < TN; j++) acc[i][j] += a[i] * b[j];
        }
        __syncthreads();
    }

#pragma unroll
    for (int i = 0; i < TM; i++) {
        int gr = rowBase + trow * TM + i;
        if (gr < M) {
            float4 v = make_float4(acc[i][0], acc[i][1], acc[i][2], acc[i][3]);
            *(float4*)(C + (size_t)gr * Nc + colBase + tcol * TN) = v;
        }
    }
}

// ---------------- edge scatter: out[dst] += coef[e] * hr[src] ---------------
// One thread handles 4 consecutive columns of one edge.
__global__ void scatter_kernel(const float* __restrict__ hr,
                               const int* __restrict__ src, const int* __restrict__ dst,
                               const float* __restrict__ coef,
                               float* __restrict__ out, int E, int dout4) {
    int idx = blockIdx.x * blockDim.x + threadIdx.x;
    if (idx >= E * dout4) return;
    int e  = idx / dout4;
    int c4 = (idx - e * dout4) * 4;
    int s = src[e], d = dst[e];
    float cf = coef[e];
    int dout = dout4 * 4;
    float4 v = *(const float4*)(hr + (size_t)s * dout + c4);
    float* o = out + (size_t)d * dout + c4;
    atomicAdd(o + 0, cf * v.x);
    atomicAdd(o + 1, cf * v.y);
    atomicAdd(o + 2, cf * v.z);
    atomicAdd(o + 3, cf * v.w);
}

// ---------------- bias (summed over relations) + optional relu --------------
__global__ void bias_relu_kernel(float* __restrict__ h, const float* __restrict__ b,
                                 int n, int dout, int do_relu) {
    int i = blockIdx.x * blockDim.x + threadIdx.x;
    if (i >= n) return;
    int c = i & (dout - 1);  // dout is a power of two
    float v = h[i] + b[c] + b[dout + c] + b[2 * dout + c];
    h[i] = do_relu ? fmaxf(v, 0.0f) : v;
}

// ---------------- edge-score MLP --------------------------------------------
// score = relu(concat(h[s],h[d]) @ Wp1 + bp1) @ Wp2 + bp2
__global__ __launch_bounds__(128) void edge_mlp_kernel(
    const float* __restrict__ h,
    const int* __restrict__ src, const int* __restrict__ dst,
    const float* __restrict__ Wp1, const float* __restrict__ bp1,
    const float* __restrict__ Wp2, const float* __restrict__ bp2,
    float* __restrict__ out, int EP) {
    __shared__ float sW1[128 * 64];
    __shared__ float sb1[64];
    __shared__ float sW2[64];
    __shared__ float sb2;
    for (int i = threadIdx.x; i < 128 * 64; i += 128) sW1[i] = Wp1[i];
    if (threadIdx.x < 64) {
        sb1[threadIdx.x] = bp1[threadIdx.x];
        sW2[threadIdx.x] = Wp2[threadIdx.x];
    }
    if (threadIdx.x == 0) sb2 = bp2[0];
    __syncthreads();

    int e = blockIdx.x * 128 + threadIdx.x;
    if (e >= EP) return;
    int s = src[e], d = dst[e];

    float hid[64];
#pragma unroll
    for (int j = 0; j < 64; j++) hid[j] = sb1[j];

    const float* hs = h + (size_t)s * 64;
#pragma unroll 4
    for (int k = 0; k < 64; k++) {
        float zk = __ldg(hs + k);
        const float* w = &sW1[k * 64];
#pragma unroll
        for (int j = 0; j < 64; j++) hid[j] += zk * w[j];
    }
    const float* hd = h + (size_t)d * 64;
#pragma unroll 4
    for (int k = 0; k < 64; k++) {
        float zk = __ldg(hd + k);
        const float* w = &sW1[(64 + k) * 64];
#pragma unroll
        for (int j = 0; j < 64; j++) hid[j] += zk * w[j];
    }

    float sc = sb2;
#pragma unroll
    for (int j = 0; j < 64; j++) sc += fmaxf(hid[j], 0.0f) * sW2[j];
    out[e] = sc;
}

// ---------------- host-side layer driver ------------------------------------
static void run_layer(const float* A, const float* Wl, const float* bl,
                      float* hr, float* outbuf,
                      const int* rel_src, const int* rel_dst, const float* coef,
                      int N, int E, int din, int dout, int do_relu) {
    int n = N * dout;
    zero_kernel<<<(n + 255) / 256, 256>>>(outbuf, n);
    for (int r = 0; r < RREL; r++) {
        dim3 grid(dout / BN, (N + BM - 1) / BM);
        sgemm_kernel<<<grid, 256>>>(A, Wl + (size_t)r * din * dout, hr, N, din, dout);
        int total = E * (dout / 4);
        scatter_kernel<<<(total + 255) / 256, 256>>>(
            hr, rel_src + r * E, rel_dst + r * E, coef + r * E, outbuf, E, dout / 4);
    }
    bias_relu_kernel<<<(n + 255) / 256, 256>>>(outbuf, bl, n, dout, do_relu);
}

// ---------------- entry -----------------------------------------------------
extern "C" void kernel_launch(void* const* d_in, const int* in_sizes, int n_in,
                              void* d_out, int out_size) {
    const float* x       = (const float*)d_in[0];
    const int*   rel_src = (const int*)d_in[1];
    const int*   rel_dst = (const int*)d_in[2];
    const int*   pos_src = (const int*)d_in[3];
    const int*   pos_dst = (const int*)d_in[4];
    const int*   neg_src = (const int*)d_in[5];
    const int*   neg_dst = (const int*)d_in[6];
    const float* W0 = (const float*)d_in[7];
    const float* b0 = (const float*)d_in[8];
    const float* W1 = (const float*)d_in[9];
    const float* b1 = (const float*)d_in[10];
    const float* W2 = (const float*)d_in[11];
    const float* b2 = (const float*)d_in[12];
    const float* W3 = (const float*)d_in[13];
    const float* b3 = (const float*)d_in[14];
    const float* Wp1 = (const float*)d_in[15];
    const float* bp1 = (const float*)d_in[16];
    const float* Wp2 = (const float*)d_in[17];
    const float* bp2 = (const float*)d_in[18];
    float* out = (float*)d_out;

    const int N  = in_sizes[0] / 512;
    const int E  = in_sizes[1] / RREL;
    const int EP = in_sizes[3];

    float *hA, *hB, *hr, *sn, *dn, *coef;
    cudaGetSymbolAddress((void**)&hA,   g_hA);
    cudaGetSymbolAddress((void**)&hB,   g_hB);
    cudaGetSymbolAddress((void**)&hr,   g_hr);
    cudaGetSymbolAddress((void**)&sn,   g_sn);
    cudaGetSymbolAddress((void**)&dn,   g_dn);
    cudaGetSymbolAddress((void**)&coef, g_coef);

    // ---- norms ----
    int rn = RREL * N;
    zero_kernel<<<(rn + 255) / 256, 256>>>(sn, rn);
    zero_kernel<<<(rn + 255) / 256, 256>>>(dn, rn);
    int re = RREL * E;
    deg_kernel<<<(re + 255) / 256, 256>>>(rel_src, rel_dst, sn, dn, E, N);
    norm_kernel<<<(rn + 255) / 256, 256>>>(sn, rn);
    norm_kernel<<<(rn + 255) / 256, 256>>>(dn, rn);
    coef_kernel<<<(re + 255) / 256, 256>>>(rel_src, rel_dst, sn, dn, coef, E, N);

    // ---- 4 hetero-GCN layers ----
    run_layer(x,  W0, b0, hr, hA, rel_src, rel_dst, coef, N, E, 512, 512, 1);
    run_layer(hA, W1, b1, hr, hB, rel_src, rel_dst, coef, N, E, 512, 256, 1);
    run_layer(hB, W2, b2, hr, hA, rel_src, rel_dst, coef, N, E, 256, 128, 1);
    run_layer(hA, W3, b3, hr, hB, rel_src, rel_dst, coef, N, E, 128, 64, 0);

    // ---- edge-score MLP: pos then neg ----
    edge_mlp_kernel<<<(EP + 127) / 128, 128>>>(hB, pos_src, pos_dst,
                                               Wp1, bp1, Wp2, bp2, out, EP);
    edge_mlp_kernel<<<(EP + 127) / 128, 128>>>(hB, neg_src, neg_dst,
                                               Wp1, bp1, Wp2, bp2, out + EP, EP);
}

// round 3
// speedup vs baseline: 1.7347x; 1.7347x over previous
#include <cuda_runtime.h>
#include <math.h>

#define NNODES 50000
#define RREL 3
#define EEDGE 50000
#define WTOTAL 1302528  // 3*(512*512 + 512*256 + 256*128 + 128*64)

// ---------------- scratch (device globals; no allocation allowed) ----------
__device__ float g_hA[(size_t)NNODES * 512];
__device__ float g_hB[(size_t)NNODES * 512];
__device__ float g_hr[(size_t)NNODES * 512];
__device__ float g_xr[(size_t)NNODES * 512];
__device__ float g_Wr[WTOTAL];
__device__ float g_sn[RREL * NNODES];
__device__ float g_dn[RREL * NNODES];
__device__ float g_coef[RREL * EEDGE];

// ---------------- helpers ---------------------------------------------------
__device__ __forceinline__ float tf32_rne(float x) {
    unsigned u;
    asm("cvt.rna.tf32.f32 %0, %1;" : "=r"(u) : "f"(x));
    return __uint_as_float(u);
}

__device__ __forceinline__ void mma_tf32(float c[4], const unsigned a[4], const unsigned b[2]) {
    asm volatile(
        "mma.sync.aligned.m16n8k8.row.col.f32.tf32.tf32.f32 "
        "{%0,%1,%2,%3}, {%4,%5,%6,%7}, {%8,%9}, {%0,%1,%2,%3};\n"
        : "+f"(c[0]), "+f"(c[1]), "+f"(c[2]), "+f"(c[3])
        : "r"(a[0]), "r"(a[1]), "r"(a[2]), "r"(a[3]), "r"(b[0]), "r"(b[1]));
}

// ---------------- small utility kernels ------------------------------------
__global__ void zero_kernel(float* __restrict__ p, int n) {
    int i = blockIdx.x * blockDim.x + threadIdx.x;
    if (i < n) p[i] = 0.0f;
}

__global__ void round_tf32_kernel(const float* __restrict__ in, float* __restrict__ out, int n) {
    int i = blockIdx.x * blockDim.x + threadIdx.x;
    if (i < n) out[i] = tf32_rne(in[i]);
}

__global__ void deg_kernel(const int* __restrict__ src, const int* __restrict__ dst,
                           float* __restrict__ outdeg, float* __restrict__ indeg,
                           int E, int N) {
    int i = blockIdx.x * blockDim.x + threadIdx.x;
    if (i < RREL * E) {
        int r = i / E;
        atomicAdd(&outdeg[r * N + src[i]], 1.0f);
        atomicAdd(&indeg[r * N + dst[i]], 1.0f);
    }
}

__global__ void norm_kernel(float* __restrict__ p, int n) {
    int i = blockIdx.x * blockDim.x + threadIdx.x;
    if (i < n) p[i] = rsqrtf(fmaxf(p[i], 1.0f));
}

__global__ void coef_kernel(const int* __restrict__ src, const int* __restrict__ dst,
                            const float* __restrict__ sn, const float* __restrict__ dn,
                            float* __restrict__ coef, int E, int N) {
    int i = blockIdx.x * blockDim.x + threadIdx.x;
    if (i < RREL * E) {
        int r = i / E;
        coef[i] = sn[r * N + src[i]] * dn[r * N + dst[i]];
    }
}

// ---------------- TF32 tensor-core GEMM: C[M,Nc] = A[M,K] @ B[K,Nc] ---------
// BM=128, BN=64, BK=32. 256 threads = 8 warps (4 in M, 2 in N).
// Warp tile 32x32 = 2x4 mma.m16n8k8 tiles. A and B pre-rounded to tf32.
#define BM 128
#define BN 64
#define BK 32
#define ASTR (BK + 4)   // 36 floats per A row  (16B-aligned rows: 144B)
#define BSTR (BN + 4)   // 68 floats per B row  (16B-aligned rows: 272B)

__global__ __launch_bounds__(256, 2) void sgemm_tf32_kernel(
    const float* __restrict__ A, const float* __restrict__ B,
    float* __restrict__ C, int M, int K, int Nc) {
    __shared__ float As[BM * ASTR];
    __shared__ float Bs[BK * BSTR];

    const int tid    = threadIdx.x;
    const int warpId = tid >> 5;
    const int lane   = tid & 31;
    const int g      = lane >> 2;   // 0..7
    const int tig    = lane & 3;    // 0..3
    const int wm     = warpId & 3;  // 0..3 (M)
    const int wn     = warpId >> 2; // 0..1 (N)
    const int rowBase = blockIdx.y * BM;
    const int colBase = blockIdx.x * BN;

    float acc[2][4][4];
#pragma unroll
    for (int mm = 0; mm < 2; mm++)
#pragma unroll
        for (int nn = 0; nn < 4; nn++)
#pragma unroll
            for (int i = 0; i < 4; i++) acc[mm][nn][i] = 0.0f;

    for (int k0 = 0; k0 < K; k0 += BK) {
        // A tile: 128x32 floats = 1024 float4 (4 per thread)
#pragma unroll
        for (int t = 0; t < 4; t++) {
            int i  = tid + t * 256;
            int r  = i >> 3;            // 0..127
            int kc = (i & 7) << 2;      // 0,4,...,28
            int gr = rowBase + r;
            float4 v = make_float4(0.f, 0.f, 0.f, 0.f);
            if (gr < M) v = *(const float4*)(A + (size_t)gr * K + k0 + kc);
            *(float4*)&As[r * ASTR + kc] = v;
        }
        // B tile: 32x64 floats = 512 float4 (2 per thread)
#pragma unroll
        for (int t = 0; t < 2; t++) {
            int i  = tid + t * 256;
            int kr = i >> 4;            // 0..31
            int nc = (i & 15) << 2;     // 0..60
            float4 v = *(const float4*)(B + (size_t)(k0 + kr) * Nc + colBase + nc);
            *(float4*)&Bs[kr * BSTR + nc] = v;
        }
        __syncthreads();

#pragma unroll
        for (int ks = 0; ks < BK; ks += 8) {
            unsigned a[2][4], b[4][2];
#pragma unroll
            for (int mm = 0; mm < 2; mm++) {
                const float* p = &As[(wm * 32 + mm * 16 + g) * ASTR + ks];
                a[mm][0] = __float_as_uint(p[tig]);
                a[mm][1] = __float_as_uint(p[8 * ASTR + tig]);
                a[mm][2] = __float_as_uint(p[tig + 4]);
                a[mm][3] = __float_as_uint(p[8 * ASTR + tig + 4]);
            }
#pragma unroll
            for (int nn = 0; nn < 4; nn++) {
                int c = wn * 32 + nn * 8 + g;
                b[nn][0] = __float_as_uint(Bs[(ks + tig) * BSTR + c]);
                b[nn][1] = __float_as_uint(Bs[(ks + tig + 4) * BSTR + c]);
            }
#pragma unroll
            for (int mm = 0; mm < 2; mm++)
#pragma unroll
                for (int nn = 0; nn < 4; nn++)
                    mma_tf32(acc[mm][nn], a[mm], b[nn]);
        }
        __syncthreads();
    }

#pragma unroll
    for (int mm = 0; mm < 2; mm++) {
        int r0 = rowBase + wm * 32 + mm * 16 + g;
#pragma unroll
        for (int nn = 0; nn < 4; nn++) {
            int c = colBase + wn * 32 + nn * 8 + tig * 2;
            if (r0 < M)
                *(float2*)(C + (size_t)r0 * Nc + c) = make_float2(acc[mm][nn][0], acc[mm][nn][1]);
            if (r0 + 8 < M)
                *(float2*)(C + (size_t)(r0 + 8) * Nc + c) = make_float2(acc[mm][nn][2], acc[mm][nn][3]);
        }
    }
}

// ---------------- edge scatter: out[dst] += coef[e] * hr[src] ---------------
__global__ void scatter_kernel(const float* __restrict__ hr,
                               const int* __restrict__ src, const int* __restrict__ dst,
                               const float* __restrict__ coef,
                               float* __restrict__ out, int E, int dout4) {
    int idx = blockIdx.x * blockDim.x + threadIdx.x;
    if (idx >= E * dout4) return;
    int e  = idx / dout4;
    int c4 = (idx - e * dout4) * 4;
    int s = src[e], d = dst[e];
    float cf = coef[e];
    int dout = dout4 * 4;
    float4 v = *(const float4*)(hr + (size_t)s * dout + c4);
    float* o = out + (size_t)d * dout + c4;
    atomicAdd(o + 0, cf * v.x);
    atomicAdd(o + 1, cf * v.y);
    atomicAdd(o + 2, cf * v.z);
    atomicAdd(o + 3, cf * v.w);
}

// ---------------- bias + relu + (tf32 round for next layer's GEMM) ----------
__global__ void bias_relu_kernel(float* __restrict__ h, const float* __restrict__ b,
                                 int n, int dout, int relu_round) {
    int i = blockIdx.x * blockDim.x + threadIdx.x;
    if (i >= n) return;
    int c = i & (dout - 1);
    float v = h[i] + b[c] + b[dout + c] + b[2 * dout + c];
    if (relu_round) v = tf32_rne(fmaxf(v, 0.0f));
    h[i] = v;
}

// ---------------- edge-score MLP --------------------------------------------
__global__ __launch_bounds__(128) void edge_mlp_kernel(
    const float* __restrict__ h,
    const int* __restrict__ src, const int* __restrict__ dst,
    const float* __restrict__ Wp1, const float* __restrict__ bp1,
    const float* __restrict__ Wp2, const float* __restrict__ bp2,
    float* __restrict__ out, int EP) {
    __shared__ float sW1[128 * 64];
    __shared__ float sb1[64];
    __shared__ float sW2[64];
    __shared__ float sb2;
    for (int i = threadIdx.x; i < 128 * 64; i += 128) sW1[i] = Wp1[i];
    if (threadIdx.x < 64) {
        sb1[threadIdx.x] = bp1[threadIdx.x];
        sW2[threadIdx.x] = Wp2[threadIdx.x];
    }
    if (threadIdx.x == 0) sb2 = bp2[0];
    __syncthreads();

    int e = blockIdx.x * 128 + threadIdx.x;
    if (e >= EP) return;
    int s = src[e], d = dst[e];

    float hid[64];
#pragma unroll
    for (int j = 0; j < 64; j++) hid[j] = sb1[j];

    const float* hs = h + (size_t)s * 64;
#pragma unroll 4
    for (int k = 0; k < 64; k++) {
        float zk = __ldg(hs + k);
        const float* w = &sW1[k * 64];
#pragma unroll
        for (int j = 0; j < 64; j++) hid[j] += zk * w[j];
    }
    const float* hd = h + (size_t)d * 64;
#pragma unroll 4
    for (int k = 0; k < 64; k++) {
        float zk = __ldg(hd + k);
        const float* w = &sW1[(64 + k) * 64];
#pragma unroll
        for (int j = 0; j < 64; j++) hid[j] += zk * w[j];
    }

    float sc = sb2;
#pragma unroll
    for (int j = 0; j < 64; j++) sc += fmaxf(hid[j], 0.0f) * sW2[j];
    out[e] = sc;
}

// ---------------- host-side layer driver ------------------------------------
static void run_layer(const float* A, const float* Wl, const float* bl,
                      float* hr, float* outbuf,
                      const int* rel_src, const int* rel_dst, const float* coef,
                      int N, int E, int din, int dout, int relu_round) {
    int n = N * dout;
    zero_kernel<<<(n + 255) / 256, 256>>>(outbuf, n);
    for (int r = 0; r < RREL; r++) {
        dim3 grid(dout / BN, (N + BM - 1) / BM);
        sgemm_tf32_kernel<<<grid, 256>>>(A, Wl + (size_t)r * din * dout, hr, N, din, dout);
        int total = E * (dout / 4);
        scatter_kernel<<<(total + 255) / 256, 256>>>(
            hr, rel_src + r * E, rel_dst + r * E, coef + r * E, outbuf, E, dout / 4);
    }
    bias_relu_kernel<<<(n + 255) / 256, 256>>>(outbuf, bl, n, dout, relu_round);
}

// ---------------- entry -----------------------------------------------------
extern "C" void kernel_launch(void* const* d_in, const int* in_sizes, int n_in,
                              void* d_out, int out_size) {
    const float* x       = (const float*)d_in[0];
    const int*   rel_src = (const int*)d_in[1];
    const int*   rel_dst = (const int*)d_in[2];
    const int*   pos_src = (const int*)d_in[3];
    const int*   pos_dst = (const int*)d_in[4];
    const int*   neg_src = (const int*)d_in[5];
    const int*   neg_dst = (const int*)d_in[6];
    const float* W0 = (const float*)d_in[7];
    const float* b0 = (const float*)d_in[8];
    const float* W1 = (const float*)d_in[9];
    const float* b1 = (const float*)d_in[10];
    const float* W2 = (const float*)d_in[11];
    const float* b2 = (const float*)d_in[12];
    const float* W3 = (const float*)d_in[13];
    const float* b3 = (const float*)d_in[14];
    const float* Wp1 = (const float*)d_in[15];
    const float* bp1 = (const float*)d_in[16];
    const float* Wp2 = (const float*)d_in[17];
    const float* bp2 = (const float*)d_in[18];
    float* out = (float*)d_out;

    const int N  = in_sizes[0] / 512;
    const int E  = in_sizes[1] / RREL;
    const int EP = in_sizes[3];

    float *hA, *hB, *hr, *xr, *Wr, *sn, *dn, *coef;
    cudaGetSymbolAddress((void**)&hA,   g_hA);
    cudaGetSymbolAddress((void**)&hB,   g_hB);
    cudaGetSymbolAddress((void**)&hr,   g_hr);
    cudaGetSymbolAddress((void**)&xr,   g_xr);
    cudaGetSymbolAddress((void**)&Wr,   g_Wr);
    cudaGetSymbolAddress((void**)&sn,   g_sn);
    cudaGetSymbolAddress((void**)&dn,   g_dn);
    cudaGetSymbolAddress((void**)&coef, g_coef);

    // ---- norms ----
    int rn = RREL * N;
    zero_kernel<<<(rn + 255) / 256, 256>>>(sn, rn);
    zero_kernel<<<(rn + 255) / 256, 256>>>(dn, rn);
    int re = RREL * E;
    deg_kernel<<<(re + 255) / 256, 256>>>(rel_src, rel_dst, sn, dn, E, N);
    norm_kernel<<<(rn + 255) / 256, 256>>>(sn, rn);
    norm_kernel<<<(rn + 255) / 256, 256>>>(dn, rn);
    coef_kernel<<<(re + 255) / 256, 256>>>(rel_src, rel_dst, sn, dn, coef, E, N);

    // ---- pre-round inputs and weights to tf32 (RNE) ----
    {
        int n = N * 512;
        round_tf32_kernel<<<(n + 255) / 256, 256>>>(x, xr, n);
        int w0 = RREL * 512 * 512, w1 = RREL * 512 * 256, w2 = RREL * 256 * 128, w3 = RREL * 128 * 64;
        round_tf32_kernel<<<(w0 + 255) / 256, 256>>>(W0, Wr, w0);
        round_tf32_kernel<<<(w1 + 255) / 256, 256>>>(W1, Wr + w0, w1);
        round_tf32_kernel<<<(w2 + 255) / 256, 256>>>(W2, Wr + w0 + w1, w2);
        round_tf32_kernel<<<(w3 + 255) / 256, 256>>>(W3, Wr + w0 + w1 + w2, w3);
    }
    const float* W0r = Wr;
    const float* W1r = Wr + RREL * 512 * 512;
    const float* W2r = W1r + RREL * 512 * 256;
    const float* W3r = W2r + RREL * 256 * 128;

    // ---- 4 hetero-GCN layers ----
    run_layer(xr, W0r, b0, hr, hA, rel_src, rel_dst, coef, N, E, 512, 512, 1);
    run_layer(hA, W1r, b1, hr, hB, rel_src, rel_dst, coef, N, E, 512, 256, 1);
    run_layer(hB, W2r, b2, hr, hA, rel_src, rel_dst, coef, N, E, 256, 128, 1);
    run_layer(hA, W3r, b3, hr, hB, rel_src, rel_dst, coef, N, E, 128, 64, 0);

    // ---- edge-score MLP: pos then neg ----
    edge_mlp_kernel<<<(EP + 127) / 128, 128>>>(hB, pos_src, pos_dst,
                                               Wp1, bp1, Wp2, bp2, out, EP);
    edge_mlp_kernel<<<(EP + 127) / 128, 128>>>(hB, neg_src, neg_dst,
                                               Wp1, bp1, Wp2, bp2, out + EP, EP);
}

// round 5
// speedup vs baseline: 2.0338x; 1.1724x over previous
#include <cuda_runtime.h>
#include <cstdint>
#include <math.h>

#define NNODES 50000
#define RREL 3
#define EEDGE 50000
#define WTOTAL 1302528  // 3*(512*512 + 512*256 + 256*128 + 128*64)

// ---------------- scratch (device globals; no allocation allowed) ----------
__device__ float g_hA[(size_t)NNODES * 512];
__device__ float g_hB[(size_t)NNODES * 512];
__device__ float g_hr[(size_t)NNODES * 1536];   // GEMM out: [N, 3*dout] concat
__device__ float g_xr[(size_t)NNODES * 512];    // tf32-rounded input
__device__ float g_Bc[WTOTAL];                  // packed weights Bcat[K, 3*dout], tf32
__device__ float g_sn[RREL * NNODES];
__device__ float g_dn[RREL * NNODES];
__device__ float g_coef[RREL * EEDGE];

// ---------------- helpers ---------------------------------------------------
__device__ __forceinline__ float tf32_rne(float x) {
    unsigned u;
    asm("cvt.rna.tf32.f32 %0, %1;" : "=r"(u) : "f"(x));
    return __uint_as_float(u);
}

__device__ __forceinline__ void mma_tf32(float c[4], const unsigned a[4], const unsigned b[2]) {
    asm volatile(
        "mma.sync.aligned.m16n8k8.row.col.f32.tf32.tf32.f32 "
        "{%0,%1,%2,%3}, {%4,%5,%6,%7}, {%8,%9}, {%0,%1,%2,%3};\n"
        : "+f"(c[0]), "+f"(c[1]), "+f"(c[2]), "+f"(c[3])
        : "r"(a[0]), "r"(a[1]), "r"(a[2]), "r"(a[3]), "r"(b[0]), "r"(b[1]));
}

__device__ __forceinline__ uint32_t smem_u32(const void* p) {
    uint32_t a;
    asm("{ .reg .u64 t; cvta.to.shared.u64 t, %1; cvt.u32.u64 %0, t; }" : "=r"(a) : "l"(p));
    return a;
}

__device__ __forceinline__ void cp_async16(uint32_t dst, const void* src, bool pred) {
    int b = pred ? 16 : 0;
    asm volatile("cp.async.cg.shared.global [%0], [%1], 16, %2;\n"
                 :: "r"(dst), "l"(src), "r"(b));
}
#define CP_COMMIT() asm volatile("cp.async.commit_group;\n" ::: "memory")
#define CP_WAIT(n)  asm volatile("cp.async.wait_group %0;\n" :: "n"(n) : "memory")

// ---------------- small utility kernels ------------------------------------
__global__ void zero_kernel(float* __restrict__ p, int n) {
    int i = blockIdx.x * blockDim.x + threadIdx.x;
    if (i < n) p[i] = 0.0f;
}

__global__ void round_tf32_kernel(const float* __restrict__ in, float* __restrict__ out, int n) {
    int i = blockIdx.x * blockDim.x + threadIdx.x;
    if (i < n) out[i] = tf32_rne(in[i]);
}

// pack W[r, k, c] -> Bcat[k, r*dout + c], tf32-rounded. Bcat is [K, Ncat] row-major.
__global__ void pack_w_kernel(const float* __restrict__ W, float* __restrict__ out,
                              int din, int dout) {
    int i = blockIdx.x * blockDim.x + threadIdx.x;
    int Ncat = RREL * dout;
    int total = din * Ncat;
    if (i >= total) return;
    int k = i / Ncat;
    int n = i - k * Ncat;
    int r = n / dout;
    int c = n - r * dout;
    out[i] = tf32_rne(W[((size_t)r * din + k) * dout + c]);
}

__global__ void deg_kernel(const int* __restrict__ src, const int* __restrict__ dst,
                           float* __restrict__ outdeg, float* __restrict__ indeg,
                           int E, int N) {
    int i = blockIdx.x * blockDim.x + threadIdx.x;
    if (i < RREL * E) {
        int r = i / E;
        atomicAdd(&outdeg[r * N + src[i]], 1.0f);
        atomicAdd(&indeg[r * N + dst[i]], 1.0f);
    }
}

__global__ void norm_kernel(float* __restrict__ p, int n) {
    int i = blockIdx.x * blockDim.x + threadIdx.x;
    if (i < n) p[i] = rsqrtf(fmaxf(p[i], 1.0f));
}

__global__ void coef_kernel(const int* __restrict__ src, const int* __restrict__ dst,
                            const float* __restrict__ sn, const float* __restrict__ dn,
                            float* __restrict__ coef, int E, int N) {
    int i = blockIdx.x * blockDim.x + threadIdx.x;
    if (i < RREL * E) {
        int r = i / E;
        coef[i] = sn[r * N + src[i]] * dn[r * N + dst[i]];
    }
}

// ---------------- TF32 tensor-core GEMM with cp.async pipeline --------------
// C[M,Nc] = A[M,K] @ B[K,Nc].  BM=128, BN=128, BK=32, 2-stage double buffer.
// 256 threads = 8 warps (4 in M x 2 in N); warp tile 32x64 = 2x8 mma m16n8k8.
#define BM 128
#define BN 128
#define BK 32
#define ASTR 36    // floats per A smem row  (144 B, 16B-aligned)
#define BSTR 132   // floats per B smem row  (528 B, 16B-aligned)
#define A_STAGE (BM * ASTR)            // 4608 floats
#define B_STAGE (BK * BSTR)            // 4224 floats
#define STAGE_FLOATS (A_STAGE + B_STAGE)
#define GEMM_SMEM_BYTES (2 * STAGE_FLOATS * 4)   // 70656

__device__ __forceinline__ void issue_stage_loads(
    uint32_t sAs, uint32_t sBs,
    const float* __restrict__ A, const float* __restrict__ B,
    int M, int K, int Nc, int rowBase, int colBase, int k0, int tid) {
    // A: 128 rows x 32 floats = 1024 float4, 4 per thread
#pragma unroll
    for (int t = 0; t < 4; t++) {
        int i  = tid + t * 256;
        int r  = i >> 3;
        int kc = (i & 7) << 2;
        int gr = rowBase + r;
        cp_async16(sAs + (uint32_t)(r * ASTR + kc) * 4,
                   A + (size_t)gr * K + k0 + kc, gr < M);
    }
    // B: 32 rows x 128 floats = 1024 float4, 4 per thread
#pragma unroll
    for (int t = 0; t < 4; t++) {
        int i  = tid + t * 256;
        int kr = i >> 5;
        int nc = (i & 31) << 2;
        cp_async16(sBs + (uint32_t)(kr * BSTR + nc) * 4,
                   B + (size_t)(k0 + kr) * Nc + colBase + nc, colBase + nc < Nc);
    }
}

__global__ void __launch_bounds__(256, 2) gemm_tf32_pipe_kernel(
    const float* __restrict__ A, const float* __restrict__ B,
    float* __restrict__ C, int M, int K, int Nc) {
    extern __shared__ float smem[];
    float* As[2] = {smem, smem + STAGE_FLOATS};
    float* Bs[2] = {smem + A_STAGE, smem + STAGE_FLOATS + A_STAGE};
    uint32_t sA[2] = {smem_u32(As[0]), smem_u32(As[1])};
    uint32_t sB[2] = {smem_u32(Bs[0]), smem_u32(Bs[1])};

    const int tid    = threadIdx.x;
    const int warpId = tid >> 5;
    const int lane   = tid & 31;
    const int g      = lane >> 2;   // 0..7
    const int tig    = lane & 3;    // 0..3
    const int wm     = warpId & 3;  // 0..3 (M)
    const int wn     = warpId >> 2; // 0..1 (N)
    const int rowBase = blockIdx.y * BM;
    const int colBase = blockIdx.x * BN;

    float acc[2][8][4];
#pragma unroll
    for (int mm = 0; mm < 2; mm++)
#pragma unroll
        for (int nn = 0; nn < 8; nn++)
#pragma unroll
            for (int i = 0; i < 4; i++) acc[mm][nn][i] = 0.0f;

    const int nk = K >> 5;  // K is a multiple of 32
    issue_stage_loads(sA[0], sB[0], A, B, M, K, Nc, rowBase, colBase, 0, tid);
    CP_COMMIT();

    for (int i = 0; i < nk; i++) {
        int buf = i & 1;
        if (i + 1 < nk) {
            issue_stage_loads(sA[buf ^ 1], sB[buf ^ 1], A, B, M, K, Nc,
                              rowBase, colBase, (i + 1) << 5, tid);
            CP_COMMIT();
            CP_WAIT(1);
        } else {
            CP_WAIT(0);
        }
        __syncthreads();

        const float* __restrict__ as = As[buf];
        const float* __restrict__ bs = Bs[buf];
#pragma unroll
        for (int ks = 0; ks < BK; ks += 8) {
            unsigned a[2][4], b[8][2];
#pragma unroll
            for (int mm = 0; mm < 2; mm++) {
                const float* p = &as[(wm * 32 + mm * 16 + g) * ASTR + ks];
                a[mm][0] = __float_as_uint(p[tig]);
                a[mm][1] = __float_as_uint(p[8 * ASTR + tig]);
                a[mm][2] = __float_as_uint(p[tig + 4]);
                a[mm][3] = __float_as_uint(p[8 * ASTR + tig + 4]);
            }
#pragma unroll
            for (int nn = 0; nn < 8; nn++) {
                int c = wn * 64 + nn * 8 + g;
                b[nn][0] = __float_as_uint(bs[(ks + tig) * BSTR + c]);
                b[nn][1] = __float_as_uint(bs[(ks + tig + 4) * BSTR + c]);
            }
#pragma unroll
            for (int mm = 0; mm < 2; mm++)
#pragma unroll
                for (int nn = 0; nn < 8; nn++)
                    mma_tf32(acc[mm][nn], a[mm], b[nn]);
        }
        __syncthreads();
    }

#pragma unroll
    for (int mm = 0; mm < 2; mm++) {
        int r0 = rowBase + wm * 32 + mm * 16 + g;
#pragma unroll
        for (int nn = 0; nn < 8; nn++) {
            int c = colBase + wn * 64 + nn * 8 + tig * 2;
            if (c < Nc) {
                if (r0 < M)
                    *(float2*)(C + (size_t)r0 * Nc + c) =
                        make_float2(acc[mm][nn][0], acc[mm][nn][1]);
                if (r0 + 8 < M)
                    *(float2*)(C + (size_t)(r0 + 8) * Nc + c) =
                        make_float2(acc[mm][nn][2], acc[mm][nn][3]);
            }
        }
    }
}

// ---------------- edge scatter: out[dst] += coef[e] * hr[src] ---------------
__global__ void scatter_kernel(const float* __restrict__ hr,
                               const int* __restrict__ src, const int* __restrict__ dst,
                               const float* __restrict__ coef,
                               float* __restrict__ out, int E, int dout4,
                               int hr_stride, int hr_off) {
    int idx = blockIdx.x * blockDim.x + threadIdx.x;
    if (idx >= E * dout4) return;
    int e  = idx / dout4;
    int c4 = (idx - e * dout4) * 4;
    int s = src[e], d = dst[e];
    float cf = coef[e];
    int dout = dout4 * 4;
    float4 v = *(const float4*)(hr + (size_t)s * hr_stride + hr_off + c4);
    float* o = out + (size_t)d * dout + c4;
    atomicAdd(o + 0, cf * v.x);
    atomicAdd(o + 1, cf * v.y);
    atomicAdd(o + 2, cf * v.z);
    atomicAdd(o + 3, cf * v.w);
}

// ---------------- bias + relu + (tf32 round for next layer's GEMM) ----------
__global__ void bias_relu_kernel(float* __restrict__ h, const float* __restrict__ b,
                                 int n, int dout, int relu_round) {
    int i = blockIdx.x * blockDim.x + threadIdx.x;
    if (i >= n) return;
    int c = i & (dout - 1);
    float v = h[i] + b[c] + b[dout + c] + b[2 * dout + c];
    if (relu_round) v = tf32_rne(fmaxf(v, 0.0f));
    h[i] = v;
}

// ---------------- edge-score MLP --------------------------------------------
__global__ __launch_bounds__(128) void edge_mlp_kernel(
    const float* __restrict__ h,
    const int* __restrict__ src, const int* __restrict__ dst,
    const float* __restrict__ Wp1, const float* __restrict__ bp1,
    const float* __restrict__ Wp2, const float* __restrict__ bp2,
    float* __restrict__ out, int EP) {
    __shared__ float sW1[128 * 64];
    __shared__ float sb1[64];
    __shared__ float sW2[64];
    __shared__ float sb2;
    for (int i = threadIdx.x; i < 128 * 64; i += 128) sW1[i] = Wp1[i];
    if (threadIdx.x < 64) {
        sb1[threadIdx.x] = bp1[threadIdx.x];
        sW2[threadIdx.x] = Wp2[threadIdx.x];
    }
    if (threadIdx.x == 0) sb2 = bp2[0];
    __syncthreads();

    int e = blockIdx.x * 128 + threadIdx.x;
    if (e >= EP) return;
    int s = src[e], d = dst[e];

    float hid[64];
#pragma unroll
    for (int j = 0; j < 64; j++) hid[j] = sb1[j];

    const float* hs = h + (size_t)s * 64;
#pragma unroll 4
    for (int k = 0; k < 64; k++) {
        float zk = __ldg(hs + k);
        const float* w = &sW1[k * 64];
#pragma unroll
        for (int j = 0; j < 64; j++) hid[j] += zk * w[j];
    }
    const float* hd = h + (size_t)d * 64;
#pragma unroll 4
    for (int k = 0; k < 64; k++) {
        float zk = __ldg(hd + k);
        const float* w = &sW1[(64 + k) * 64];
#pragma unroll
        for (int j = 0; j < 64; j++) hid[j] += zk * w[j];
    }

    float sc = sb2;
#pragma unroll
    for (int j = 0; j < 64; j++) sc += fmaxf(hid[j], 0.0f) * sW2[j];
    out[e] = sc;
}

// ---------------- host-side layer driver ------------------------------------
static void run_layer(const float* A, const float* Bc, const float* bl,
                      float* hr, float* outbuf,
                      const int* rel_src, const int* rel_dst, const float* coef,
                      int N, int E, int din, int dout, int relu_round) {
    int Ncat = RREL * dout;
    int n = N * dout;
    zero_kernel<<<(n + 255) / 256, 256>>>(outbuf, n);
    dim3 grid((Ncat + BN - 1) / BN, (N + BM - 1) / BM);
    gemm_tf32_pipe_kernel<<<grid, 256, GEMM_SMEM_BYTES>>>(A, Bc, hr, N, din, Ncat);
    for (int r = 0; r < RREL; r++) {
        int total = E * (dout / 4);
        scatter_kernel<<<(total + 255) / 256, 256>>>(
            hr, rel_src + r * E, rel_dst + r * E, coef + r * E, outbuf,
            E, dout / 4, Ncat, r * dout);
    }
    bias_relu_kernel<<<(n + 255) / 256, 256>>>(outbuf, bl, n, dout, relu_round);
}

// ---------------- entry -----------------------------------------------------
extern "C" void kernel_launch(void* const* d_in, const int* in_sizes, int n_in,
                              void* d_out, int out_size) {
    const float* x       = (const float*)d_in[0];
    const int*   rel_src = (const int*)d_in[1];
    const int*   rel_dst = (const int*)d_in[2];
    const int*   pos_src = (const int*)d_in[3];
    const int*   pos_dst = (const int*)d_in[4];
    const int*   neg_src = (const int*)d_in[5];
    const int*   neg_dst = (const int*)d_in[6];
    const float* W0 = (const float*)d_in[7];
    const float* b0 = (const float*)d_in[8];
    const float* W1 = (const float*)d_in[9];
    const float* b1 = (const float*)d_in[10];
    const float* W2 = (const float*)d_in[11];
    const float* b2 = (const float*)d_in[12];
    const float* W3 = (const float*)d_in[13];
    const float* b3 = (const float*)d_in[14];
    const float* Wp1 = (const float*)d_in[15];
    const float* bp1 = (const float*)d_in[16];
    const float* Wp2 = (const float*)d_in[17];
    const float* bp2 = (const float*)d_in[18];
    float* out = (float*)d_out;

    const int N  = in_sizes[0] / 512;
    const int E  = in_sizes[1] / RREL;
    const int EP = in_sizes[3];

    cudaFuncSetAttribute(gemm_tf32_pipe_kernel,
                         cudaFuncAttributeMaxDynamicSharedMemorySize, GEMM_SMEM_BYTES);

    float *hA, *hB, *hr, *xr, *Bc, *sn, *dn, *coef;
    cudaGetSymbolAddress((void**)&hA,   g_hA);
    cudaGetSymbolAddress((void**)&hB,   g_hB);
    cudaGetSymbolAddress((void**)&hr,   g_hr);
    cudaGetSymbolAddress((void**)&xr,   g_xr);
    cudaGetSymbolAddress((void**)&Bc,   g_Bc);
    cudaGetSymbolAddress((void**)&sn,   g_sn);
    cudaGetSymbolAddress((void**)&dn,   g_dn);
    cudaGetSymbolAddress((void**)&coef, g_coef);

    // ---- norms ----
    int rn = RREL * N;
    zero_kernel<<<(rn + 255) / 256, 256>>>(sn, rn);
    zero_kernel<<<(rn + 255) / 256, 256>>>(dn, rn);
    int re = RREL * E;
    deg_kernel<<<(re + 255) / 256, 256>>>(rel_src, rel_dst, sn, dn, E, N);
    norm_kernel<<<(rn + 255) / 256, 256>>>(sn, rn);
    norm_kernel<<<(rn + 255) / 256, 256>>>(dn, rn);
    coef_kernel<<<(re + 255) / 256, 256>>>(rel_src, rel_dst, sn, dn, coef, E, N);

    // ---- round input + pack concat weights (tf32 RNE) ----
    {
        int n = N * 512;
        round_tf32_kernel<<<(n + 255) / 256, 256>>>(x, xr, n);
    }
    float* Bc0 = Bc;
    float* Bc1 = Bc0 + RREL * 512 * 512;
    float* Bc2 = Bc1 + RREL * 512 * 256;
    float* Bc3 = Bc2 + RREL * 256 * 128;
    {
        int t0 = RREL * 512 * 512, t1 = RREL * 512 * 256, t2 = RREL * 256 * 128, t3 = RREL * 128 * 64;
        pack_w_kernel<<<(t0 + 255) / 256, 256>>>(W0, Bc0, 512, 512);
        pack_w_kernel<<<(t1 + 255) / 256, 256>>>(W1, Bc1, 512, 256);
        pack_w_kernel<<<(t2 + 255) / 256, 256>>>(W2, Bc2, 256, 128);
        pack_w_kernel<<<(t3 + 255) / 256, 256>>>(W3, Bc3, 128, 64);
    }

    // ---- 4 hetero-GCN layers ----
    run_layer(xr, Bc0, b0, hr, hA, rel_src, rel_dst, coef, N, E, 512, 512, 1);
    run_layer(hA, Bc1, b1, hr, hB, rel_src, rel_dst, coef, N, E, 512, 256, 1);
    run_layer(hB, Bc2, b2, hr, hA, rel_src, rel_dst, coef, N, E, 256, 128, 1);
    run_layer(hA, Bc3, b3, hr, hB, rel_src, rel_dst, coef, N, E, 128, 64, 0);

    // ---- edge-score MLP: pos then neg ----
    edge_mlp_kernel<<<(EP + 127) / 128, 128>>>(hB, pos_src, pos_dst,
                                               Wp1, bp1, Wp2, bp2, out, EP);
    edge_mlp_kernel<<<(EP + 127) / 128, 128>>>(hB, neg_src, neg_dst,
                                               Wp1, bp1, Wp2, bp2, out + EP, EP);
}

// round 7
// speedup vs baseline: 2.0439x; 1.0049x over previous
#include <cuda_runtime.h>
#include <cstdint>
#include <math.h>

#define NNODES 50000
#define RREL 3
#define EEDGE 50000
#define WTOTAL 1302528  // 3*(512*512 + 512*256 + 256*128 + 128*64)

// ---------------- scratch (device globals; no allocation allowed) ----------
__device__ float g_hA[(size_t)NNODES * 512];
__device__ float g_hB[(size_t)NNODES * 512];
__device__ float g_hr[(size_t)NNODES * 1536];   // GEMM out: [N, 3*dout] concat
__device__ float g_xr[(size_t)NNODES * 512];    // tf32-rounded input
__device__ float g_Bc[WTOTAL];                  // packed weights Bcat[K, 3*dout], tf32
__device__ float g_sn[RREL * NNODES];
__device__ float g_dn[RREL * NNODES];
__device__ float g_coef[RREL * EEDGE];

// ---------------- helpers ---------------------------------------------------
__device__ __forceinline__ float tf32_rne(float x) {
    unsigned u;
    asm("cvt.rna.tf32.f32 %0, %1;" : "=r"(u) : "f"(x));
    return __uint_as_float(u);
}

__device__ __forceinline__ void mma_tf32(float c[4], const unsigned a[4], const unsigned b[2]) {
    asm volatile(
        "mma.sync.aligned.m16n8k8.row.col.f32.tf32.tf32.f32 "
        "{%0,%1,%2,%3}, {%4,%5,%6,%7}, {%8,%9}, {%0,%1,%2,%3};\n"
        : "+f"(c[0]), "+f"(c[1]), "+f"(c[2]), "+f"(c[3])
        : "r"(a[0]), "r"(a[1]), "r"(a[2]), "r"(a[3]), "r"(b[0]), "r"(b[1]));
}

__device__ __forceinline__ uint32_t smem_u32(const void* p) {
    uint32_t a;
    asm("{ .reg .u64 t; cvta.to.shared.u64 t, %1; cvt.u32.u64 %0, t; }" : "=r"(a) : "l"(p));
    return a;
}

__device__ __forceinline__ void cp_async16(uint32_t dst, const void* src, bool pred) {
    int b = pred ? 16 : 0;
    asm volatile("cp.async.cg.shared.global [%0], [%1], 16, %2;\n"
                 :: "r"(dst), "l"(src), "r"(b));
}
#define CP_COMMIT() asm volatile("cp.async.commit_group;\n" ::: "memory")
#define CP_WAIT(n)  asm volatile("cp.async.wait_group %0;\n" :: "n"(n) : "memory")

// ---------------- small utility kernels ------------------------------------
__global__ void zero_kernel(float* __restrict__ p, int n) {
    int i = blockIdx.x * blockDim.x + threadIdx.x;
    if (i < n) p[i] = 0.0f;
}

// init outbuf with the sum of per-relation biases (folds bias add)
__global__ void biasinit_kernel(float* __restrict__ p, const float* __restrict__ b,
                                int n, int dout) {
    int i = blockIdx.x * blockDim.x + threadIdx.x;
    if (i >= n) return;
    int c = i & (dout - 1);
    p[i] = b[c] + b[dout + c] + b[2 * dout + c];
}

__global__ void round_tf32_kernel(const float* __restrict__ in, float* __restrict__ out, int n) {
    int i = blockIdx.x * blockDim.x + threadIdx.x;
    if (i < n) out[i] = tf32_rne(in[i]);
}

// pack W[r, k, c] -> Bcat[k, r*dout + c], tf32-rounded. Bcat is [K, Ncat] row-major.
__global__ void pack_w_kernel(const float* __restrict__ W, float* __restrict__ out,
                              int din, int dout) {
    int i = blockIdx.x * blockDim.x + threadIdx.x;
    int Ncat = RREL * dout;
    int total = din * Ncat;
    if (i >= total) return;
    int k = i / Ncat;
    int n = i - k * Ncat;
    int r = n / dout;
    int c = n - r * dout;
    out[i] = tf32_rne(W[((size_t)r * din + k) * dout + c]);
}

__global__ void deg_kernel(const int* __restrict__ src, const int* __restrict__ dst,
                           float* __restrict__ outdeg, float* __restrict__ indeg,
                           int E, int N) {
    int i = blockIdx.x * blockDim.x + threadIdx.x;
    if (i < RREL * E) {
        int r = i / E;
        atomicAdd(&outdeg[r * N + src[i]], 1.0f);
        atomicAdd(&indeg[r * N + dst[i]], 1.0f);
    }
}

__global__ void norm_kernel(float* __restrict__ p, int n) {
    int i = blockIdx.x * blockDim.x + threadIdx.x;
    if (i < n) p[i] = rsqrtf(fmaxf(p[i], 1.0f));
}

__global__ void coef_kernel(const int* __restrict__ src, const int* __restrict__ dst,
                            const float* __restrict__ sn, const float* __restrict__ dn,
                            float* __restrict__ coef, int E, int N) {
    int i = blockIdx.x * blockDim.x + threadIdx.x;
    if (i < RREL * E) {
        int r = i / E;
        coef[i] = sn[r * N + src[i]] * dn[r * N + dst[i]];
    }
}

// ---------------- TF32 tensor-core GEMM, 3-stage cp.async pipeline ----------
// C[M,Nc] = A[M,K] @ B[K,Nc].  BM=128, BN=128, BK=32.
// 256 threads = 8 warps (4 in M x 2 in N); warp tile 32x64 = 2x8 mma m16n8k8.
#define BM 128
#define BN 128
#define BK 32
#define STAGES 3
#define ASTR 36    // floats per A smem row  (144 B, 16B-aligned)
#define BSTR 132   // floats per B smem row  (528 B, 16B-aligned)
#define A_STAGE (BM * ASTR)            // 4608 floats
#define B_STAGE (BK * BSTR)            // 4224 floats
#define STAGE_FLOATS (A_STAGE + B_STAGE)
#define GEMM_SMEM_BYTES (STAGES * STAGE_FLOATS * 4)   // 105984

__device__ __forceinline__ void issue_stage_loads(
    uint32_t sAs, uint32_t sBs,
    const float* __restrict__ A, const float* __restrict__ B,
    int M, int K, int Nc, int rowBase, int colBase, int k0, int tid) {
    // A: 128 rows x 32 floats = 1024 float4, 4 per thread
#pragma unroll
    for (int t = 0; t < 4; t++) {
        int i  = tid + t * 256;
        int r  = i >> 3;
        int kc = (i & 7) << 2;
        int gr = rowBase + r;
        cp_async16(sAs + (uint32_t)(r * ASTR + kc) * 4,
                   A + (size_t)gr * K + k0 + kc, gr < M);
    }
    // B: 32 rows x 128 floats = 1024 float4, 4 per thread
#pragma unroll
    for (int t = 0; t < 4; t++) {
        int i  = tid + t * 256;
        int kr = i >> 5;
        int nc = (i & 31) << 2;
        cp_async16(sBs + (uint32_t)(kr * BSTR + nc) * 4,
                   B + (size_t)(k0 + kr) * Nc + colBase + nc, colBase + nc < Nc);
    }
}

__global__ void __launch_bounds__(256, 2) gemm_tf32_pipe_kernel(
    const float* __restrict__ A, const float* __restrict__ B,
    float* __restrict__ C, int M, int K, int Nc) {
    extern __shared__ float smem[];
    float* As[STAGES];
    float* Bs[STAGES];
    uint32_t sA[STAGES], sB[STAGES];
#pragma unroll
    for (int s = 0; s < STAGES; s++) {
        As[s] = smem + s * STAGE_FLOATS;
        Bs[s] = As[s] + A_STAGE;
        sA[s] = smem_u32(As[s]);
        sB[s] = smem_u32(Bs[s]);
    }

    const int tid    = threadIdx.x;
    const int warpId = tid >> 5;
    const int lane   = tid & 31;
    const int g      = lane >> 2;   // 0..7
    const int tig    = lane & 3;    // 0..3
    const int wm     = warpId & 3;  // 0..3 (M)
    const int wn     = warpId >> 2; // 0..1 (N)
    const int rowBase = blockIdx.y * BM;
    const int colBase = blockIdx.x * BN;

    float acc[2][8][4];
#pragma unroll
    for (int mm = 0; mm < 2; mm++)
#pragma unroll
        for (int nn = 0; nn < 8; nn++)
#pragma unroll
            for (int i = 0; i < 4; i++) acc[mm][nn][i] = 0.0f;

    const int nk = K >> 5;  // K is a multiple of 32, nk >= 4
    // prologue: issue first STAGES-1 = 2 chunks
    issue_stage_loads(sA[0], sB[0], A, B, M, K, Nc, rowBase, colBase, 0, tid);
    CP_COMMIT();
    issue_stage_loads(sA[1], sB[1], A, B, M, K, Nc, rowBase, colBase, 32, tid);
    CP_COMMIT();

    int buf = 0;
    for (int i = 0; i < nk; i++) {
        // complete chunk i's group; keep at most one newer group pending
        if (i + 1 < nk) { CP_WAIT(1); } else { CP_WAIT(0); }
        __syncthreads();   // also guarantees compute(i-1) done before reusing its buffer

        if (i + STAGES - 1 < nk) {
            int nb = buf + (STAGES - 1); if (nb >= STAGES) nb -= STAGES;
            issue_stage_loads(sA[nb], sB[nb], A, B, M, K, Nc,
                              rowBase, colBase, (i + STAGES - 1) << 5, tid);
            CP_COMMIT();
        }

        const float* __restrict__ as = As[buf];
        const float* __restrict__ bs = Bs[buf];
#pragma unroll
        for (int ks = 0; ks < BK; ks += 8) {
            unsigned a[2][4], b[8][2];
#pragma unroll
            for (int mm = 0; mm < 2; mm++) {
                const float* p = &as[(wm * 32 + mm * 16 + g) * ASTR + ks];
                a[mm][0] = __float_as_uint(p[tig]);
                a[mm][1] = __float_as_uint(p[8 * ASTR + tig]);
                a[mm][2] = __float_as_uint(p[tig + 4]);
                a[mm][3] = __float_as_uint(p[8 * ASTR + tig + 4]);
            }
#pragma unroll
            for (int nn = 0; nn < 8; nn++) {
                int c = wn * 64 + nn * 8 + g;
                b[nn][0] = __float_as_uint(bs[(ks + tig) * BSTR + c]);
                b[nn][1] = __float_as_uint(bs[(ks + tig + 4) * BSTR + c]);
            }
#pragma unroll
            for (int mm = 0; mm < 2; mm++)
#pragma unroll
                for (int nn = 0; nn < 8; nn++)
                    mma_tf32(acc[mm][nn], a[mm], b[nn]);
        }
        buf++; if (buf >= STAGES) buf -= STAGES;
    }

#pragma unroll
    for (int mm = 0; mm < 2; mm++) {
        int r0 = rowBase + wm * 32 + mm * 16 + g;
#pragma unroll
        for (int nn = 0; nn < 8; nn++) {
            int c = colBase + wn * 64 + nn * 8 + tig * 2;
            if (c < Nc) {
                if (r0 < M)
                    *(float2*)(C + (size_t)r0 * Nc + c) =
                        make_float2(acc[mm][nn][0], acc[mm][nn][1]);
                if (r0 + 8 < M)
                    *(float2*)(C + (size_t)(r0 + 8) * Nc + c) =
                        make_float2(acc[mm][nn][2], acc[mm][nn][3]);
            }
        }
    }
}

// ---------------- fused edge scatter over all relations ---------------------
// out[dst] += coef[e] * hr[src, r*dout : (r+1)*dout]
__global__ void scatter_all_kernel(const float* __restrict__ hr,
                                   const int* __restrict__ src, const int* __restrict__ dst,
                                   const float* __restrict__ coef,
                                   float* __restrict__ out, int E, int dout4,
                                   int hr_stride) {
    int idx = blockIdx.x * blockDim.x + threadIdx.x;
    if (idx >= RREL * E * dout4) return;
    int eg = idx / dout4;            // 0 .. RREL*E-1  (r*E + e)
    int c4 = (idx - eg * dout4) * 4;
    int r  = eg / E;
    int s = src[eg], d = dst[eg];
    float cf = coef[eg];
    int dout = dout4 * 4;
    float4 v = *(const float4*)(hr + (size_t)s * hr_stride + r * dout + c4);
    float* o = out + (size_t)d * dout + c4;
    atomicAdd(o + 0, cf * v.x);
    atomicAdd(o + 1, cf * v.y);
    atomicAdd(o + 2, cf * v.z);
    atomicAdd(o + 3, cf * v.w);
}

// ---------------- relu + tf32 round (bias already folded into init) ---------
__global__ void relu_round_kernel(float* __restrict__ h, int n, int relu_round) {
    int i = blockIdx.x * blockDim.x + threadIdx.x;
    if (i >= n) return;
    if (relu_round) h[i] = tf32_rne(fmaxf(h[i], 0.0f));
}

// ---------------- edge-score MLP --------------------------------------------
__global__ __launch_bounds__(128) void edge_mlp_kernel(
    const float* __restrict__ h,
    const int* __restrict__ src, const int* __restrict__ dst,
    const float* __restrict__ Wp1, const float* __restrict__ bp1,
    const float* __restrict__ Wp2, const float* __restrict__ bp2,
    float* __restrict__ out, int EP) {
    __shared__ float sW1[128 * 64];
    __shared__ float sb1[64];
    __shared__ float sW2[64];
    __shared__ float sb2;
    for (int i = threadIdx.x; i < 128 * 64; i += 128) sW1[i] = Wp1[i];
    if (threadIdx.x < 64) {
        sb1[threadIdx.x] = bp1[threadIdx.x];
        sW2[threadIdx.x] = Wp2[threadIdx.x];
    }
    if (threadIdx.x == 0) sb2 = bp2[0];
    __syncthreads();

    int e = blockIdx.x * 128 + threadIdx.x;
    if (e >= EP) return;
    int s = src[e], d = dst[e];

    float hid[64];
#pragma unroll
    for (int j = 0; j < 64; j++) hid[j] = sb1[j];

    const float* hs = h + (size_t)s * 64;
#pragma unroll 4
    for (int k = 0; k < 64; k++) {
        float zk = __ldg(hs + k);
        const float* w = &sW1[k * 64];
#pragma unroll
        for (int j = 0; j < 64; j++) hid[j] += zk * w[j];
    }
    const float* hd = h + (size_t)d * 64;
#pragma unroll 4
    for (int k = 0; k < 64; k++) {
        float zk = __ldg(hd + k);
        const float* w = &sW1[(64 + k) * 64];
#pragma unroll
        for (int j = 0; j < 64; j++) hid[j] += zk * w[j];
    }

    float sc = sb2;
#pragma unroll
    for (int j = 0; j < 64; j++) sc += fmaxf(hid[j], 0.0f) * sW2[j];
    out[e] = sc;
}

// ---------------- host-side layer driver ------------------------------------
static void run_layer(const float* A, const float* Bc, const float* bl,
                      float* hr, float* outbuf,
                      const int* rel_src, const int* rel_dst, const float* coef,
                      int N, int E, int din, int dout, int relu_round) {
    int Ncat = RREL * dout;
    int n = N * dout;
    biasinit_kernel<<<(n + 255) / 256, 256>>>(outbuf, bl, n, dout);
    dim3 grid((Ncat + BN - 1) / BN, (N + BM - 1) / BM);
    gemm_tf32_pipe_kernel<<<grid, 256, GEMM_SMEM_BYTES>>>(A, Bc, hr, N, din, Ncat);
    int total = RREL * E * (dout / 4);
    scatter_all_kernel<<<(total + 255) / 256, 256>>>(
        hr, rel_src, rel_dst, coef, outbuf, E, dout / 4, Ncat);
    relu_round_kernel<<<(n + 255) / 256, 256>>>(outbuf, n, relu_round);
}

// ---------------- entry -----------------------------------------------------
extern "C" void kernel_launch(void* const* d_in, const int* in_sizes, int n_in,
                              void* d_out, int out_size) {
    const float* x       = (const float*)d_in[0];
    const int*   rel_src = (const int*)d_in[1];
    const int*   rel_dst = (const int*)d_in[2];
    const int*   pos_src = (const int*)d_in[3];
    const int*   pos_dst = (const int*)d_in[4];
    const int*   neg_src = (const int*)d_in[5];
    const int*   neg_dst = (const int*)d_in[6];
    const float* W0 = (const float*)d_in[7];
    const float* b0 = (const float*)d_in[8];
    const float* W1 = (const float*)d_in[9];
    const float* b1 = (const float*)d_in[10];
    const float* W2 = (const float*)d_in[11];
    const float* b2 = (const float*)d_in[12];
    const float* W3 = (const float*)d_in[13];
    const float* b3 = (const float*)d_in[14];
    const float* Wp1 = (const float*)d_in[15];
    const float* bp1 = (const float*)d_in[16];
    const float* Wp2 = (const float*)d_in[17];
    const float* bp2 = (const float*)d_in[18];
    float* out = (float*)d_out;

    const int N  = in_sizes[0] / 512;
    const int E  = in_sizes[1] / RREL;
    const int EP = in_sizes[3];

    cudaFuncSetAttribute(gemm_tf32_pipe_kernel,
                         cudaFuncAttributeMaxDynamicSharedMemorySize, GEMM_SMEM_BYTES);

    float *hA, *hB, *hr, *xr, *Bc, *sn, *dn, *coef;
    cudaGetSymbolAddress((void**)&hA,   g_hA);
    cudaGetSymbolAddress((void**)&hB,   g_hB);
    cudaGetSymbolAddress((void**)&hr,   g_hr);
    cudaGetSymbolAddress((void**)&xr,   g_xr);
    cudaGetSymbolAddress((void**)&Bc,   g_Bc);
    cudaGetSymbolAddress((void**)&sn,   g_sn);
    cudaGetSymbolAddress((void**)&dn,   g_dn);
    cudaGetSymbolAddress((void**)&coef, g_coef);

    // ---- norms ----
    int rn = RREL * N;
    zero_kernel<<<(rn + 255) / 256, 256>>>(sn, rn);
    zero_kernel<<<(rn + 255) / 256, 256>>>(dn, rn);
    int re = RREL * E;
    deg_kernel<<<(re + 255) / 256, 256>>>(rel_src, rel_dst, sn, dn, E, N);
    norm_kernel<<<(rn + 255) / 256, 256>>>(sn, rn);
    norm_kernel<<<(rn + 255) / 256, 256>>>(dn, rn);
    coef_kernel<<<(re + 255) / 256, 256>>>(rel_src, rel_dst, sn, dn, coef, E, N);

    // ---- round input + pack concat weights (tf32 RNE) ----
    {
        int n = N * 512;
        round_tf32_kernel<<<(n + 255) / 256, 256>>>(x, xr, n);
    }
    float* Bc0 = Bc;
    float* Bc1 = Bc0 + RREL * 512 * 512;
    float* Bc2 = Bc1 + RREL * 512 * 256;
    float* Bc3 = Bc2 + RREL * 256 * 128;
    {
        int t0 = RREL * 512 * 512, t1 = RREL * 512 * 256, t2 = RREL * 256 * 128, t3 = RREL * 128 * 64;
        pack_w_kernel<<<(t0 + 255) / 256, 256>>>(W0, Bc0, 512, 512);
        pack_w_kernel<<<(t1 + 255) / 256, 256>>>(W1, Bc1, 512, 256);
        pack_w_kernel<<<(t2 + 255) / 256, 256>>>(W2, Bc2, 256, 128);
        pack_w_kernel<<<(t3 + 255) / 256, 256>>>(W3, Bc3, 128, 64);
    }

    // ---- 4 hetero-GCN layers ----
    run_layer(xr, Bc0, b0, hr, hA, rel_src, rel_dst, coef, N, E, 512, 512, 1);
    run_layer(hA, Bc1, b1, hr, hB, rel_src, rel_dst, coef, N, E, 512, 256, 1);
    run_layer(hB, Bc2, b2, hr, hA, rel_src, rel_dst, coef, N, E, 256, 128, 1);
    run_layer(hA, Bc3, b3, hr, hB, rel_src, rel_dst, coef, N, E, 128, 64, 0);

    // ---- edge-score MLP: pos then neg ----
    edge_mlp_kernel<<<(EP + 127) / 128, 128>>>(hB, pos_src, pos_dst,
                                               Wp1, bp1, Wp2, bp2, out, EP);
    edge_mlp_kernel<<<(EP + 127) / 128, 128>>>(hB, neg_src, neg_dst,
                                               Wp1, bp1, Wp2, bp2, out + EP, EP);
}